// round 8
// baseline (speedup 1.0000x reference)
#include <cuda_runtime.h>
#include <cuda_fp16.h>
#include <cstdint>

#define Nn 8192
#define Mm 128
#define EPSf 1e-4f
#define LDA 136   // fp16 elems per smem tile row (128 + 8 pad)
#define LDL 132   // float words per label smem row (128 + 4 pad)

// ---------------- device scratch (allocation-free) ----------------
static __device__ __half g_A16[(size_t)Nn * Mm];  // out2 fp16
static __device__ __half g_B16[(size_t)Nn * Mm];  // out1 fp16
static __device__ float  g_Z[Nn];
static __device__ float  g_W[Nn];
static __device__ float  g_rZ[Nn];
static __device__ float  g_rW[Nn];
static __device__ double g_loss;

__device__ __forceinline__ uint32_t smem_u32(const void* p) {
    uint32_t a;
    asm("{ .reg .u64 t; cvta.to.shared.u64 t, %1; cvt.u32.u64 %0, t; }" : "=r"(a) : "l"(p));
    return a;
}
__device__ __forceinline__ void ldmx4(uint32_t* r, uint32_t addr) {
    asm volatile("ldmatrix.sync.aligned.m8n8.x4.shared.b16 {%0,%1,%2,%3}, [%4];"
                 : "=r"(r[0]), "=r"(r[1]), "=r"(r[2]), "=r"(r[3]) : "r"(addr));
}
__device__ __forceinline__ void mma16816(float* c, const uint32_t* a, uint32_t b0, uint32_t b1) {
    asm volatile(
        "mma.sync.aligned.m16n8k16.row.col.f32.f16.f16.f32 "
        "{%0,%1,%2,%3}, {%4,%5,%6,%7}, {%8,%9}, {%0,%1,%2,%3};"
        : "+f"(c[0]), "+f"(c[1]), "+f"(c[2]), "+f"(c[3])
        : "r"(a[0]), "r"(a[1]), "r"(a[2]), "r"(a[3]), "r"(b0), "r"(b1));
}
#define CP_ASYNC16(dst, src) \
    asm volatile("cp.async.cg.shared.global [%0], [%1], 16;" :: "r"(dst), "l"(src))
#define CP_COMMIT()  asm volatile("cp.async.commit_group;")
#define CP_WAIT(n)   asm volatile("cp.async.wait_group %0;" :: "n"(n))

__global__ void prep_kernel(const float* __restrict__ out1, const float* __restrict__ out2) {
    int t = blockIdx.x * blockDim.x + threadIdx.x;
    if (t < Nn * Mm / 4) {
        float4 a = *(const float4*)&out2[(size_t)t * 4];
        float4 b = *(const float4*)&out1[(size_t)t * 4];
        __half2 a0 = __float22half2_rn(make_float2(a.x, a.y));
        __half2 a1 = __float22half2_rn(make_float2(a.z, a.w));
        __half2 b0 = __float22half2_rn(make_float2(b.x, b.y));
        __half2 b1 = __float22half2_rn(make_float2(b.z, b.w));
        *(uint2*)&g_A16[(size_t)t * 4] = make_uint2(*(uint32_t*)&a0, *(uint32_t*)&a1);
        *(uint2*)&g_B16[(size_t)t * 4] = make_uint2(*(uint32_t*)&b0, *(uint32_t*)&b1);
    }
    if (t < Nn) { g_Z[t] = 0.0f; g_W[t] = 0.0f; }
    if (t == 0) g_loss = 0.0;
}

#define T_ELEMS (128 * LDA)                      // halfs per tile
#define AB_BYTES (2 * T_ELEMS * 2)               // 69632
#define L_BYTES  (128 * LDL * 4)                 // 67584
#define SMEM_P1  AB_BYTES
#define SMEM_P2  (AB_BYTES + L_BYTES)            // 137216

// cp.async tile loader: A,B 128 rows of fp16 (256 B/row) -> padded smem (512 thr)
__device__ __forceinline__ void load_tiles_async(uint32_t sA, uint32_t sB,
                                                 int i0, int j0, int tid) {
    #pragma unroll 4
    for (int t = tid; t < 2048; t += 512) {
        int row = t >> 4, q = (t & 15) * 8;
        CP_ASYNC16(sA + (uint32_t)((row * LDA + q) * 2), &g_A16[(size_t)(i0 + row) * Mm + q]);
        CP_ASYNC16(sB + (uint32_t)((row * LDA + q) * 2), &g_B16[(size_t)(j0 + row) * Mm + q]);
    }
}

// MMA body for warp tile 32(m) x 32(n): c[2][4][4]
__device__ __forceinline__ void mma_tile(uint32_t sA, uint32_t sB,
                                         int m0w, int n0w, int lane, float c[2][4][4]) {
    const int aro = (lane & 7) + ((lane >> 3) & 1) * 8;
    const int ako = ((lane >> 4) & 1) * 8;
    const int bro = (lane & 7) + ((lane >> 4) & 1) * 8;
    const int bko = ((lane >> 3) & 1) * 8;

    const uint32_t aoff = (uint32_t)(((m0w + aro) * LDA + ako) * 2);
    uint32_t boff[2];
    #pragma unroll
    for (int p = 0; p < 2; p++)
        boff[p] = (uint32_t)(((n0w + p * 16 + bro) * LDA + bko) * 2);

    #pragma unroll
    for (int kk = 0; kk < 8; kk++) {
        const uint32_t kb = (uint32_t)(kk * 32);
        uint32_t av[2][4], bv[2][4];
        #pragma unroll
        for (int mt = 0; mt < 2; mt++)
            ldmx4(av[mt], sA + aoff + (uint32_t)(mt * 16 * LDA * 2) + kb);
        #pragma unroll
        for (int p = 0; p < 2; p++)
            ldmx4(bv[p], sB + boff[p] + kb);
        #pragma unroll
        for (int mt = 0; mt < 2; mt++)
            #pragma unroll
            for (int nt = 0; nt < 4; nt++) {
                const int p = nt >> 1, r = (nt & 1) * 2;
                mma16816(c[mt][nt], av[mt], bv[p][r], bv[p][r + 1]);
            }
    }
}

// ---------------- Pass 1: GEMM -> exp -> row/col sums ----------------
__global__ __launch_bounds__(512, 1) void pass1_sums() {
    extern __shared__ char sm[];
    const uint32_t sA = smem_u32(sm);
    const uint32_t sB = sA + T_ELEMS * 2;

    const int tid = threadIdx.x, wid = tid >> 5, lane = tid & 31;
    const int i0 = blockIdx.y * 128, j0 = blockIdx.x * 128;
    const int m0w = (wid & 3) * 32, n0w = (wid >> 2) * 32;

    load_tiles_async(sA, sB, i0, j0, tid);
    CP_COMMIT();
    CP_WAIT(0);
    __syncthreads();

    float c[2][4][4] = {};
    mma_tile(sA, sB, m0w, n0w, lane, c);

    #pragma unroll
    for (int mt = 0; mt < 2; mt++)
        #pragma unroll
        for (int nt = 0; nt < 4; nt++)
            #pragma unroll
            for (int q = 0; q < 4; q++) c[mt][nt][q] = __expf(c[mt][nt][q]);

    // row sums
    #pragma unroll
    for (int mt = 0; mt < 2; mt++) {
        float r0 = 0.f, r1 = 0.f;
        #pragma unroll
        for (int nt = 0; nt < 4; nt++) {
            r0 += c[mt][nt][0] + c[mt][nt][1];
            r1 += c[mt][nt][2] + c[mt][nt][3];
        }
        r0 += __shfl_xor_sync(0xFFFFFFFF, r0, 1);
        r0 += __shfl_xor_sync(0xFFFFFFFF, r0, 2);
        r1 += __shfl_xor_sync(0xFFFFFFFF, r1, 1);
        r1 += __shfl_xor_sync(0xFFFFFFFF, r1, 2);
        if ((lane & 3) == 0) {
            atomicAdd(&g_Z[i0 + m0w + mt * 16 + (lane >> 2)], r0);
            atomicAdd(&g_Z[i0 + m0w + mt * 16 + 8 + (lane >> 2)], r1);
        }
    }
    // col sums
    #pragma unroll
    for (int nt = 0; nt < 4; nt++) {
        float v0 = c[0][nt][0] + c[0][nt][2] + c[1][nt][0] + c[1][nt][2];
        float v1 = c[0][nt][1] + c[0][nt][3] + c[1][nt][1] + c[1][nt][3];
        v0 += __shfl_xor_sync(0xFFFFFFFF, v0, 4);
        v0 += __shfl_xor_sync(0xFFFFFFFF, v0, 8);
        v0 += __shfl_xor_sync(0xFFFFFFFF, v0, 16);
        v1 += __shfl_xor_sync(0xFFFFFFFF, v1, 4);
        v1 += __shfl_xor_sync(0xFFFFFFFF, v1, 8);
        v1 += __shfl_xor_sync(0xFFFFFFFF, v1, 16);
        if (lane < 4) {
            int col = j0 + n0w + nt * 8 + lane * 2;
            atomicAdd(&g_W[col], v0);
            atomicAdd(&g_W[col + 1], v1);
        }
    }
}

__global__ void recip_kernel() {
    int i = blockIdx.x * blockDim.x + threadIdx.x;
    if (i < Nn) { g_rZ[i] = 1.0f / g_Z[i]; g_rW[i] = 1.0f / g_W[i]; }
}

// ---------------- Pass 2: cp.async tiles+label, GEMM, fused loss ----------------
__global__ __launch_bounds__(512, 1) void pass2_fused(const float* __restrict__ label) {
    extern __shared__ char sm[];
    const uint32_t sA = smem_u32(sm);
    const uint32_t sB = sA + T_ELEMS * 2;
    float* Lt = (float*)(sm + AB_BYTES);
    const uint32_t sL = sB + T_ELEMS * 2;

    const int tid = threadIdx.x, wid = tid >> 5, lane = tid & 31;
    const int i0 = blockIdx.y * 128, j0 = blockIdx.x * 128;
    const int m0w = (wid & 3) * 32, n0w = (wid >> 2) * 32;

    // group 0: A/B tiles
    load_tiles_async(sA, sB, i0, j0, tid);
    CP_COMMIT();
    // group 1: label tile (128 x 128 f32), in flight during MMA
    #pragma unroll 8
    for (int t = tid; t < 4096; t += 512) {
        int row = t >> 5, cx = (t & 31) * 4;
        CP_ASYNC16(sL + (uint32_t)((row * LDL + cx) * 4),
                   &label[(size_t)(i0 + row) * Nn + j0 + cx]);
    }
    CP_COMMIT();

    CP_WAIT(1);          // tiles ready; label still streaming
    __syncthreads();

    float c[2][4][4] = {};
    mma_tile(sA, sB, m0w, n0w, lane, c);

    CP_WAIT(0);          // label ready (latency hidden behind MMA)
    __syncthreads();

    float acc = 0.f;
    #pragma unroll
    for (int mt = 0; mt < 2; mt++) {
        const int rl = m0w + mt * 16 + (lane >> 2);
        const float rZ0 = g_rZ[i0 + rl], rZ8 = g_rZ[i0 + rl + 8];
        #pragma unroll
        for (int nt = 0; nt < 4; nt++) {
            const int lcol = n0w + nt * 8 + (lane & 3) * 2;
            const float rw0 = g_rW[j0 + lcol], rw1 = g_rW[j0 + lcol + 1];
            float2 l0 = *(const float2*)&Lt[rl * LDL + lcol];
            float2 l1 = *(const float2*)&Lt[(rl + 8) * LDL + lcol];

            float e0 = __expf(c[mt][nt][0]);
            float e1 = __expf(c[mt][nt][1]);
            float e2 = __expf(c[mt][nt][2]);
            float e3 = __expf(c[mt][nt][3]);

            acc += l0.x * __logf(fmaf(e0, rZ0, EPSf) * fmaf(e0, rw0, EPSf));
            acc += l0.y * __logf(fmaf(e1, rZ0, EPSf) * fmaf(e1, rw1, EPSf));
            acc += l1.x * __logf(fmaf(e2, rZ8, EPSf) * fmaf(e2, rw0, EPSf));
            acc += l1.y * __logf(fmaf(e3, rZ8, EPSf) * fmaf(e3, rw1, EPSf));
        }
    }

    __syncthreads();
    float* red = (float*)sm;
    acc += __shfl_xor_sync(0xFFFFFFFF, acc, 16);
    acc += __shfl_xor_sync(0xFFFFFFFF, acc, 8);
    acc += __shfl_xor_sync(0xFFFFFFFF, acc, 4);
    acc += __shfl_xor_sync(0xFFFFFFFF, acc, 2);
    acc += __shfl_xor_sync(0xFFFFFFFF, acc, 1);
    if (lane == 0) red[wid] = acc;
    __syncthreads();
    if (tid == 0) {
        float s = 0.f;
        #pragma unroll
        for (int w = 0; w < 16; w++) s += red[w];
        atomicAdd(&g_loss, -(double)s);
    }
}

__global__ void final_kernel(float* out) { out[0] = (float)g_loss; }

extern "C" void kernel_launch(void* const* d_in, const int* in_sizes, int n_in,
                              void* d_out, int out_size) {
    const float* out1  = (const float*)d_in[0];
    const float* out2  = (const float*)d_in[1];
    const float* label = (const float*)d_in[2];

    cudaFuncSetAttribute(pass1_sums, cudaFuncAttributeMaxDynamicSharedMemorySize, SMEM_P1);
    cudaFuncSetAttribute(pass2_fused, cudaFuncAttributeMaxDynamicSharedMemorySize, SMEM_P2);

    prep_kernel<<<(Nn * Mm / 4 + 255) / 256, 256>>>(out1, out2);
    dim3 grid(Nn / 128, Nn / 128);
    pass1_sums<<<grid, 512, SMEM_P1>>>();
    recip_kernel<<<32, 256>>>();
    pass2_fused<<<grid, 512, SMEM_P2>>>(label);
    final_kernel<<<1, 1>>>((float*)d_out);
}

// round 9
// speedup vs baseline: 1.2820x; 1.2820x over previous
#include <cuda_runtime.h>
#include <cuda_fp16.h>
#include <cstdint>

#define Nn 8192
#define Mm 128
#define EPSf 1e-4f
#define LDA 136   // fp16 elems per smem tile row (128 + 8 pad)
#define LDL 72    // float words per half-label smem row (64 + 8 pad)

// ---------------- device scratch (allocation-free) ----------------
static __device__ __half g_A16[(size_t)Nn * Mm];  // out2 fp16
static __device__ __half g_B16[(size_t)Nn * Mm];  // out1 fp16
static __device__ float  g_Z[Nn];
static __device__ float  g_W[Nn];
static __device__ float  g_rZ[Nn];
static __device__ float  g_rW[Nn];
static __device__ double g_loss;

__device__ __forceinline__ uint32_t smem_u32(const void* p) {
    uint32_t a;
    asm("{ .reg .u64 t; cvta.to.shared.u64 t, %1; cvt.u32.u64 %0, t; }" : "=r"(a) : "l"(p));
    return a;
}
__device__ __forceinline__ void ldmx4(uint32_t* r, uint32_t addr) {
    asm volatile("ldmatrix.sync.aligned.m8n8.x4.shared.b16 {%0,%1,%2,%3}, [%4];"
                 : "=r"(r[0]), "=r"(r[1]), "=r"(r[2]), "=r"(r[3]) : "r"(addr));
}
__device__ __forceinline__ void mma16816(float* c, const uint32_t* a, uint32_t b0, uint32_t b1) {
    asm volatile(
        "mma.sync.aligned.m16n8k16.row.col.f32.f16.f16.f32 "
        "{%0,%1,%2,%3}, {%4,%5,%6,%7}, {%8,%9}, {%0,%1,%2,%3};"
        : "+f"(c[0]), "+f"(c[1]), "+f"(c[2]), "+f"(c[3])
        : "r"(a[0]), "r"(a[1]), "r"(a[2]), "r"(a[3]), "r"(b0), "r"(b1));
}
#define CP_ASYNC16(dst, src) \
    asm volatile("cp.async.cg.shared.global [%0], [%1], 16;" :: "r"(dst), "l"(src))
#define CP_COMMIT()  asm volatile("cp.async.commit_group;")
#define CP_WAIT(n)   asm volatile("cp.async.wait_group %0;" :: "n"(n))

__global__ void prep_kernel(const float* __restrict__ out1, const float* __restrict__ out2) {
    int t = blockIdx.x * blockDim.x + threadIdx.x;
    if (t < Nn * Mm / 4) {
        float4 a = *(const float4*)&out2[(size_t)t * 4];
        float4 b = *(const float4*)&out1[(size_t)t * 4];
        __half2 a0 = __float22half2_rn(make_float2(a.x, a.y));
        __half2 a1 = __float22half2_rn(make_float2(a.z, a.w));
        __half2 b0 = __float22half2_rn(make_float2(b.x, b.y));
        __half2 b1 = __float22half2_rn(make_float2(b.z, b.w));
        *(uint2*)&g_A16[(size_t)t * 4] = make_uint2(*(uint32_t*)&a0, *(uint32_t*)&a1);
        *(uint2*)&g_B16[(size_t)t * 4] = make_uint2(*(uint32_t*)&b0, *(uint32_t*)&b1);
    }
    if (t < Nn) { g_Z[t] = 0.0f; g_W[t] = 0.0f; }
    if (t == 0) g_loss = 0.0;
}

#define T_ELEMS (128 * LDA)
#define AB_BYTES (2 * T_ELEMS * 2)            // 69632
#define LHALF_BYTES (128 * LDL * 4)           // 36864
#define SMEM_P1  AB_BYTES
#define SMEM_P2  (AB_BYTES + LHALF_BYTES)     // 106496 -> 2 CTAs/SM

// plain-LDG tile loader (R6 style): A,B 128 rows of fp16 -> padded smem
__device__ __forceinline__ void load_tiles(__half* At, __half* Bt, int i0, int j0, int tid) {
    #pragma unroll 8
    for (int t = tid; t < 2048; t += 256) {
        int row = t >> 4, q = (t & 15) * 8;
        *(uint4*)&At[row * LDA + q] = *(const uint4*)&g_A16[(size_t)(i0 + row) * Mm + q];
        *(uint4*)&Bt[row * LDA + q] = *(const uint4*)&g_B16[(size_t)(j0 + row) * Mm + q];
    }
}

// ---------------- Pass 1 (R6, unchanged): GEMM -> exp -> row/col sums ----------------
__global__ __launch_bounds__(256, 2) void pass1_sums() {
    extern __shared__ char sm[];
    __half* At = (__half*)sm;
    __half* Bt = At + T_ELEMS;

    const int tid = threadIdx.x, wid = tid >> 5, lane = tid & 31;
    const int i0 = blockIdx.y * 128, j0 = blockIdx.x * 128;
    const int m0w = (wid & 3) * 32, n0w = (wid >> 2) * 64;

    load_tiles(At, Bt, i0, j0, tid);
    __syncthreads();

    float c[2][8][4] = {};

    const int aro = (lane & 7) + ((lane >> 3) & 1) * 8;
    const int ako = ((lane >> 4) & 1) * 8;
    const int bro = (lane & 7) + ((lane >> 4) & 1) * 8;
    const int bko = ((lane >> 3) & 1) * 8;
    const uint32_t sA = smem_u32(At), sB = smem_u32(Bt);
    const uint32_t aoff = (uint32_t)(((m0w + aro) * LDA + ako) * 2);
    uint32_t boff[4];
    #pragma unroll
    for (int p = 0; p < 4; p++)
        boff[p] = (uint32_t)(((n0w + p * 16 + bro) * LDA + bko) * 2);

    #pragma unroll
    for (int kk = 0; kk < 8; kk++) {
        const uint32_t kb = (uint32_t)(kk * 32);
        uint32_t av[2][4], bv[4][4];
        #pragma unroll
        for (int mt = 0; mt < 2; mt++)
            ldmx4(av[mt], sA + aoff + (uint32_t)(mt * 16 * LDA * 2) + kb);
        #pragma unroll
        for (int p = 0; p < 4; p++)
            ldmx4(bv[p], sB + boff[p] + kb);
        #pragma unroll
        for (int mt = 0; mt < 2; mt++)
            #pragma unroll
            for (int nt = 0; nt < 8; nt++) {
                const int p = nt >> 1, r = (nt & 1) * 2;
                mma16816(c[mt][nt], av[mt], bv[p][r], bv[p][r + 1]);
            }
    }

    #pragma unroll
    for (int mt = 0; mt < 2; mt++)
        #pragma unroll
        for (int nt = 0; nt < 8; nt++)
            #pragma unroll
            for (int q = 0; q < 4; q++) c[mt][nt][q] = __expf(c[mt][nt][q]);

    #pragma unroll
    for (int mt = 0; mt < 2; mt++) {
        float r0 = 0.f, r1 = 0.f;
        #pragma unroll
        for (int nt = 0; nt < 8; nt++) {
            r0 += c[mt][nt][0] + c[mt][nt][1];
            r1 += c[mt][nt][2] + c[mt][nt][3];
        }
        r0 += __shfl_xor_sync(0xFFFFFFFF, r0, 1);
        r0 += __shfl_xor_sync(0xFFFFFFFF, r0, 2);
        r1 += __shfl_xor_sync(0xFFFFFFFF, r1, 1);
        r1 += __shfl_xor_sync(0xFFFFFFFF, r1, 2);
        if ((lane & 3) == 0) {
            atomicAdd(&g_Z[i0 + m0w + mt * 16 + (lane >> 2)], r0);
            atomicAdd(&g_Z[i0 + m0w + mt * 16 + 8 + (lane >> 2)], r1);
        }
    }
    #pragma unroll
    for (int nt = 0; nt < 8; nt++) {
        float v0 = c[0][nt][0] + c[0][nt][2] + c[1][nt][0] + c[1][nt][2];
        float v1 = c[0][nt][1] + c[0][nt][3] + c[1][nt][1] + c[1][nt][3];
        v0 += __shfl_xor_sync(0xFFFFFFFF, v0, 4);
        v0 += __shfl_xor_sync(0xFFFFFFFF, v0, 8);
        v0 += __shfl_xor_sync(0xFFFFFFFF, v0, 16);
        v1 += __shfl_xor_sync(0xFFFFFFFF, v1, 4);
        v1 += __shfl_xor_sync(0xFFFFFFFF, v1, 8);
        v1 += __shfl_xor_sync(0xFFFFFFFF, v1, 16);
        if (lane < 4) {
            int col = j0 + n0w + nt * 8 + lane * 2;
            atomicAdd(&g_W[col], v0);
            atomicAdd(&g_W[col + 1], v1);
        }
    }
}

__global__ void recip_kernel() {
    int i = blockIdx.x * blockDim.x + threadIdx.x;
    if (i < Nn) { g_rZ[i] = 1.0f / g_Z[i]; g_rW[i] = 1.0f / g_W[i]; }
}

// ---------------- Pass 2: warp tile 16x128; label halves double-buffered ----------------
__global__ __launch_bounds__(256, 2) void pass2_fused(const float* __restrict__ label) {
    extern __shared__ char sm[];
    __half* At = (__half*)sm;
    __half* Bt = At + T_ELEMS;
    float* Lleft  = (float*)(sm + AB_BYTES);
    float* Lright = (float*)sm;                 // overlays tiles after MMA

    const int tid = threadIdx.x, wid = tid >> 5, lane = tid & 31;
    const int i0 = blockIdx.y * 128, j0 = blockIdx.x * 128;
    const int m0w = wid * 16;                   // 8 warps x 16 rows

    // group 0: label LEFT half (128 x 64 f32) — streams during tile load + MMA
    const uint32_t sLl = smem_u32(Lleft);
    #pragma unroll 8
    for (int t = tid; t < 2048; t += 256) {
        int row = t >> 4, cx = (t & 15) * 4;
        CP_ASYNC16(sLl + (uint32_t)((row * LDL + cx) * 4),
                   &label[(size_t)(i0 + row) * Nn + j0 + cx]);
    }
    CP_COMMIT();

    load_tiles(At, Bt, i0, j0, tid);
    __syncthreads();

    // MMA: warp tile 16(m) x 128(n)
    float c[16][4] = {};
    const int aro = (lane & 7) + ((lane >> 3) & 1) * 8;
    const int ako = ((lane >> 4) & 1) * 8;
    const int bro = (lane & 7) + ((lane >> 4) & 1) * 8;
    const int bko = ((lane >> 3) & 1) * 8;
    const uint32_t sA = smem_u32(At), sB = smem_u32(Bt);
    const uint32_t aoff = (uint32_t)(((m0w + aro) * LDA + ako) * 2);
    const uint32_t boffb = (uint32_t)((bro * LDA + bko) * 2);

    #pragma unroll
    for (int kk = 0; kk < 8; kk++) {
        const uint32_t kb = (uint32_t)(kk * 32);
        uint32_t av[4];
        ldmx4(av, sA + aoff + kb);
        #pragma unroll
        for (int p = 0; p < 8; p++) {
            uint32_t bv[4];
            ldmx4(bv, sB + boffb + (uint32_t)(p * 16 * LDA * 2) + kb);
            mma16816(c[p * 2],     av, bv[0], bv[1]);
            mma16816(c[p * 2 + 1], av, bv[2], bv[3]);
        }
    }

    __syncthreads();   // all ldmatrix done; tile smem dead

    // group 1: label RIGHT half into tile region — streams during left epilogue
    const uint32_t sLr = smem_u32(Lright);
    #pragma unroll 8
    for (int t = tid; t < 2048; t += 256) {
        int row = t >> 4, cx = (t & 15) * 4;
        CP_ASYNC16(sLr + (uint32_t)((row * LDL + cx) * 4),
                   &label[(size_t)(i0 + row) * Nn + j0 + 64 + cx]);
    }
    CP_COMMIT();

    CP_WAIT(1);        // left half landed (hidden behind tiles+MMA)
    __syncthreads();

    const int rl = m0w + (lane >> 2);
    const float rZ0 = g_rZ[i0 + rl], rZ8 = g_rZ[i0 + rl + 8];
    float acc = 0.f;

    #pragma unroll
    for (int nt = 0; nt < 8; nt++) {           // LEFT: cols 0..63
        const int lcol = nt * 8 + (lane & 3) * 2;
        const float rw0 = g_rW[j0 + lcol], rw1 = g_rW[j0 + lcol + 1];
        float2 l0 = *(const float2*)&Lleft[rl * LDL + lcol];
        float2 l1 = *(const float2*)&Lleft[(rl + 8) * LDL + lcol];
        float e0 = __expf(c[nt][0]);
        float e1 = __expf(c[nt][1]);
        float e2 = __expf(c[nt][2]);
        float e3 = __expf(c[nt][3]);
        acc += l0.x * __logf(fmaf(e0, rZ0, EPSf) * fmaf(e0, rw0, EPSf));
        acc += l0.y * __logf(fmaf(e1, rZ0, EPSf) * fmaf(e1, rw1, EPSf));
        acc += l1.x * __logf(fmaf(e2, rZ8, EPSf) * fmaf(e2, rw0, EPSf));
        acc += l1.y * __logf(fmaf(e3, rZ8, EPSf) * fmaf(e3, rw1, EPSf));
    }

    CP_WAIT(0);        // right half landed (hidden behind left epilogue)
    __syncthreads();

    #pragma unroll
    for (int nt = 8; nt < 16; nt++) {          // RIGHT: cols 64..127
        const int lcol = (nt - 8) * 8 + (lane & 3) * 2;
        const float rw0 = g_rW[j0 + 64 + lcol], rw1 = g_rW[j0 + 64 + lcol + 1];
        float2 l0 = *(const float2*)&Lright[rl * LDL + lcol];
        float2 l1 = *(const float2*)&Lright[(rl + 8) * LDL + lcol];
        float e0 = __expf(c[nt][0]);
        float e1 = __expf(c[nt][1]);
        float e2 = __expf(c[nt][2]);
        float e3 = __expf(c[nt][3]);
        acc += l0.x * __logf(fmaf(e0, rZ0, EPSf) * fmaf(e0, rw0, EPSf));
        acc += l0.y * __logf(fmaf(e1, rZ0, EPSf) * fmaf(e1, rw1, EPSf));
        acc += l1.x * __logf(fmaf(e2, rZ8, EPSf) * fmaf(e2, rw0, EPSf));
        acc += l1.y * __logf(fmaf(e3, rZ8, EPSf) * fmaf(e3, rw1, EPSf));
    }

    __syncthreads();
    float* red = (float*)sm;
    acc += __shfl_xor_sync(0xFFFFFFFF, acc, 16);
    acc += __shfl_xor_sync(0xFFFFFFFF, acc, 8);
    acc += __shfl_xor_sync(0xFFFFFFFF, acc, 4);
    acc += __shfl_xor_sync(0xFFFFFFFF, acc, 2);
    acc += __shfl_xor_sync(0xFFFFFFFF, acc, 1);
    if (lane == 0) red[wid] = acc;
    __syncthreads();
    if (tid == 0) {
        float s = 0.f;
        #pragma unroll
        for (int w = 0; w < 8; w++) s += red[w];
        atomicAdd(&g_loss, -(double)s);
    }
}

__global__ void final_kernel(float* out) { out[0] = (float)g_loss; }

extern "C" void kernel_launch(void* const* d_in, const int* in_sizes, int n_in,
                              void* d_out, int out_size) {
    const float* out1  = (const float*)d_in[0];
    const float* out2  = (const float*)d_in[1];
    const float* label = (const float*)d_in[2];

    cudaFuncSetAttribute(pass1_sums, cudaFuncAttributeMaxDynamicSharedMemorySize, SMEM_P1);
    cudaFuncSetAttribute(pass2_fused, cudaFuncAttributeMaxDynamicSharedMemorySize, SMEM_P2);

    prep_kernel<<<(Nn * Mm / 4 + 255) / 256, 256>>>(out1, out2);
    dim3 grid(Nn / 128, Nn / 128);
    pass1_sums<<<grid, 256, SMEM_P1>>>();
    recip_kernel<<<32, 256>>>();
    pass2_fused<<<grid, 256, SMEM_P2>>>(label);
    final_kernel<<<1, 1>>>((float*)d_out);
}

// round 10
// speedup vs baseline: 1.3476x; 1.0512x over previous
#include <cuda_runtime.h>
#include <cuda_fp16.h>
#include <cstdint>

#define Nn 8192
#define Mm 128
#define EPSf 1e-4f
#define LDA 136   // fp16 elems per smem tile row (128 + 8 pad)

// ---------------- device scratch (allocation-free) ----------------
static __device__ __half g_A16[(size_t)Nn * Mm];  // out2 fp16
static __device__ __half g_B16[(size_t)Nn * Mm];  // out1 fp16
static __device__ float  g_Z[Nn];
static __device__ float  g_W[Nn];
static __device__ float  g_rZ[Nn];
static __device__ float  g_rW[Nn];
static __device__ double g_loss;

__device__ __forceinline__ uint32_t smem_u32(const void* p) {
    uint32_t a;
    asm("{ .reg .u64 t; cvta.to.shared.u64 t, %1; cvt.u32.u64 %0, t; }" : "=r"(a) : "l"(p));
    return a;
}
__device__ __forceinline__ void ldmx4(uint32_t* r, uint32_t addr) {
    asm volatile("ldmatrix.sync.aligned.m8n8.x4.shared.b16 {%0,%1,%2,%3}, [%4];"
                 : "=r"(r[0]), "=r"(r[1]), "=r"(r[2]), "=r"(r[3]) : "r"(addr));
}
__device__ __forceinline__ void mma16816(float* c, const uint32_t* a, uint32_t b0, uint32_t b1) {
    asm volatile(
        "mma.sync.aligned.m16n8k16.row.col.f32.f16.f16.f32 "
        "{%0,%1,%2,%3}, {%4,%5,%6,%7}, {%8,%9}, {%0,%1,%2,%3};"
        : "+f"(c[0]), "+f"(c[1]), "+f"(c[2]), "+f"(c[3])
        : "r"(a[0]), "r"(a[1]), "r"(a[2]), "r"(a[3]), "r"(b0), "r"(b1));
}

__global__ void prep_kernel(const float* __restrict__ out1, const float* __restrict__ out2) {
    int t = blockIdx.x * blockDim.x + threadIdx.x;
    if (t < Nn * Mm / 4) {
        float4 a = *(const float4*)&out2[(size_t)t * 4];
        float4 b = *(const float4*)&out1[(size_t)t * 4];
        __half2 a0 = __float22half2_rn(make_float2(a.x, a.y));
        __half2 a1 = __float22half2_rn(make_float2(a.z, a.w));
        __half2 b0 = __float22half2_rn(make_float2(b.x, b.y));
        __half2 b1 = __float22half2_rn(make_float2(b.z, b.w));
        *(uint2*)&g_A16[(size_t)t * 4] = make_uint2(*(uint32_t*)&a0, *(uint32_t*)&a1);
        *(uint2*)&g_B16[(size_t)t * 4] = make_uint2(*(uint32_t*)&b0, *(uint32_t*)&b1);
    }
    if (t < Nn) { g_Z[t] = 0.0f; g_W[t] = 0.0f; }
    if (t == 0) g_loss = 0.0;
}

#define T_ELEMS (128 * LDA)
#define AB_BYTES (2 * T_ELEMS * 2)            // 69632
#define STAGE_BYTES (128 * 68 * 4)            // 34816 (128 rows x 68 words)
#define SMEM_P1  AB_BYTES
#define SMEM_P2  (AB_BYTES + STAGE_BYTES)     // 104448 -> 2 CTAs/SM

// tile loader: A,B 128 rows of fp16 -> padded smem
__device__ __forceinline__ void load_tiles(__half* At, __half* Bt, int i0, int j0, int tid) {
    #pragma unroll 8
    for (int t = tid; t < 2048; t += 256) {
        int row = t >> 4, q = (t & 15) * 8;
        *(uint4*)&At[row * LDA + q] = *(const uint4*)&g_A16[(size_t)(i0 + row) * Mm + q];
        *(uint4*)&Bt[row * LDA + q] = *(const uint4*)&g_B16[(size_t)(j0 + row) * Mm + q];
    }
}

// MMA body, warp tile 32(m) x 64(n): c[2][8][4]
__device__ __forceinline__ void mma_tile(uint32_t sA, uint32_t sB,
                                         int m0w, int n0w, int lane, float c[2][8][4]) {
    const int aro = (lane & 7) + ((lane >> 3) & 1) * 8;
    const int ako = ((lane >> 4) & 1) * 8;
    const int bro = (lane & 7) + ((lane >> 4) & 1) * 8;
    const int bko = ((lane >> 3) & 1) * 8;
    const uint32_t aoff = (uint32_t)(((m0w + aro) * LDA + ako) * 2);
    uint32_t boff[4];
    #pragma unroll
    for (int p = 0; p < 4; p++)
        boff[p] = (uint32_t)(((n0w + p * 16 + bro) * LDA + bko) * 2);

    #pragma unroll
    for (int kk = 0; kk < 8; kk++) {
        const uint32_t kb = (uint32_t)(kk * 32);
        uint32_t av[2][4], bv[4][4];
        #pragma unroll
        for (int mt = 0; mt < 2; mt++)
            ldmx4(av[mt], sA + aoff + (uint32_t)(mt * 16 * LDA * 2) + kb);
        #pragma unroll
        for (int p = 0; p < 4; p++)
            ldmx4(bv[p], sB + boff[p] + kb);
        #pragma unroll
        for (int mt = 0; mt < 2; mt++)
            #pragma unroll
            for (int nt = 0; nt < 8; nt++) {
                const int p = nt >> 1, r = (nt & 1) * 2;
                mma16816(c[mt][nt], av[mt], bv[p][r], bv[p][r + 1]);
            }
    }
}

// ---------------- Pass 1 (R6, unchanged): GEMM -> exp -> row/col sums ----------------
__global__ __launch_bounds__(256, 2) void pass1_sums() {
    extern __shared__ char sm[];
    __half* At = (__half*)sm;
    __half* Bt = At + T_ELEMS;

    const int tid = threadIdx.x, wid = tid >> 5, lane = tid & 31;
    const int i0 = blockIdx.y * 128, j0 = blockIdx.x * 128;
    const int m0w = (wid & 3) * 32, n0w = (wid >> 2) * 64;

    load_tiles(At, Bt, i0, j0, tid);
    __syncthreads();

    float c[2][8][4] = {};
    mma_tile(smem_u32(At), smem_u32(Bt), m0w, n0w, lane, c);

    #pragma unroll
    for (int mt = 0; mt < 2; mt++)
        #pragma unroll
        for (int nt = 0; nt < 8; nt++)
            #pragma unroll
            for (int q = 0; q < 4; q++) c[mt][nt][q] = __expf(c[mt][nt][q]);

    #pragma unroll
    for (int mt = 0; mt < 2; mt++) {
        float r0 = 0.f, r1 = 0.f;
        #pragma unroll
        for (int nt = 0; nt < 8; nt++) {
            r0 += c[mt][nt][0] + c[mt][nt][1];
            r1 += c[mt][nt][2] + c[mt][nt][3];
        }
        r0 += __shfl_xor_sync(0xFFFFFFFF, r0, 1);
        r0 += __shfl_xor_sync(0xFFFFFFFF, r0, 2);
        r1 += __shfl_xor_sync(0xFFFFFFFF, r1, 1);
        r1 += __shfl_xor_sync(0xFFFFFFFF, r1, 2);
        if ((lane & 3) == 0) {
            atomicAdd(&g_Z[i0 + m0w + mt * 16 + (lane >> 2)], r0);
            atomicAdd(&g_Z[i0 + m0w + mt * 16 + 8 + (lane >> 2)], r1);
        }
    }
    #pragma unroll
    for (int nt = 0; nt < 8; nt++) {
        float v0 = c[0][nt][0] + c[0][nt][2] + c[1][nt][0] + c[1][nt][2];
        float v1 = c[0][nt][1] + c[0][nt][3] + c[1][nt][1] + c[1][nt][3];
        v0 += __shfl_xor_sync(0xFFFFFFFF, v0, 4);
        v0 += __shfl_xor_sync(0xFFFFFFFF, v0, 8);
        v0 += __shfl_xor_sync(0xFFFFFFFF, v0, 16);
        v1 += __shfl_xor_sync(0xFFFFFFFF, v1, 4);
        v1 += __shfl_xor_sync(0xFFFFFFFF, v1, 8);
        v1 += __shfl_xor_sync(0xFFFFFFFF, v1, 16);
        if (lane < 4) {
            int col = j0 + n0w + nt * 8 + lane * 2;
            atomicAdd(&g_W[col], v0);
            atomicAdd(&g_W[col + 1], v1);
        }
    }
}

__global__ void recip_kernel() {
    int i = blockIdx.x * blockDim.x + threadIdx.x;
    if (i < Nn) { g_rZ[i] = 1.0f / g_Z[i]; g_rW[i] = 1.0f / g_W[i]; }
}

// ---------------- Pass 2: GEMM -> stage fp16 scores -> coalesced fused loss ----------------
__global__ __launch_bounds__(256, 2) void pass2_fused(const float* __restrict__ label) {
    extern __shared__ char sm[];
    __half* At = (__half*)sm;
    __half* Bt = At + T_ELEMS;
    uint32_t* stage = (uint32_t*)(sm + AB_BYTES);   // 128 rows x 68 words

    const int tid = threadIdx.x, wid = tid >> 5, lane = tid & 31;
    const int i0 = blockIdx.y * 128, j0 = blockIdx.x * 128;
    const int m0w = (wid & 3) * 32, n0w = (wid >> 2) * 64;

    load_tiles(At, Bt, i0, j0, tid);
    __syncthreads();

    float c[2][8][4] = {};
    mma_tile(smem_u32(At), smem_u32(Bt), m0w, n0w, lane, c);

    // stage fp16 scores (validated R4/R5 pattern, stride 68 words)
    #pragma unroll
    for (int mt = 0; mt < 2; mt++)
        #pragma unroll
        for (int nt = 0; nt < 8; nt++) {
            int row = m0w + mt * 16 + (lane >> 2);
            int cw  = (n0w + nt * 8 + (lane & 3) * 2) >> 1;
            __half2 p0 = __float22half2_rn(make_float2(c[mt][nt][0], c[mt][nt][1]));
            __half2 p1 = __float22half2_rn(make_float2(c[mt][nt][2], c[mt][nt][3]));
            stage[(size_t)row * 68 + cw]       = *(uint32_t*)&p0;
            stage[(size_t)(row + 8) * 68 + cw] = *(uint32_t*)&p1;
        }
    __syncthreads();

    // coalesced epilogue: half-warp per row-segment; lane16 covers 8 cols
    const int hw  = lane >> 4;      // 0..1: row parity within pair
    const int l16 = lane & 15;      // 0..15: 8-col segment
    const int colb = l16 * 8;
    float acc = 0.f;

    #pragma unroll
    for (int s8 = 0; s8 < 8; s8++) {
        const int r  = wid * 16 + s8 * 2 + hw;       // local row 0..127
        const float rZ = g_rZ[i0 + r];
        uint4 sv = *(const uint4*)&stage[(size_t)r * 68 + l16 * 4];     // 8 halves
        const float* lp = &label[(size_t)(i0 + r) * Nn + j0 + colb];
        float4 la0 = *(const float4*)lp;
        float4 la1 = *(const float4*)(lp + 4);
        float4 w0  = *(const float4*)&g_rW[j0 + colb];
        float4 w1  = *(const float4*)&g_rW[j0 + colb + 4];

        float2 s0 = __half22float2(*(__half2*)&sv.x);
        float2 s1 = __half22float2(*(__half2*)&sv.y);
        float2 s2 = __half22float2(*(__half2*)&sv.z);
        float2 s3 = __half22float2(*(__half2*)&sv.w);

        float e0 = __expf(s0.x), e1 = __expf(s0.y), e2 = __expf(s1.x), e3 = __expf(s1.y);
        float e4 = __expf(s2.x), e5 = __expf(s2.y), e6 = __expf(s3.x), e7 = __expf(s3.y);

        acc += la0.x * __logf(fmaf(e0, rZ, EPSf) * fmaf(e0, w0.x, EPSf));
        acc += la0.y * __logf(fmaf(e1, rZ, EPSf) * fmaf(e1, w0.y, EPSf));
        acc += la0.z * __logf(fmaf(e2, rZ, EPSf) * fmaf(e2, w0.z, EPSf));
        acc += la0.w * __logf(fmaf(e3, rZ, EPSf) * fmaf(e3, w0.w, EPSf));
        acc += la1.x * __logf(fmaf(e4, rZ, EPSf) * fmaf(e4, w1.x, EPSf));
        acc += la1.y * __logf(fmaf(e5, rZ, EPSf) * fmaf(e5, w1.y, EPSf));
        acc += la1.z * __logf(fmaf(e6, rZ, EPSf) * fmaf(e6, w1.z, EPSf));
        acc += la1.w * __logf(fmaf(e7, rZ, EPSf) * fmaf(e7, w1.w, EPSf));
    }

    __syncthreads();
    float* red = (float*)sm;
    acc += __shfl_xor_sync(0xFFFFFFFF, acc, 16);
    acc += __shfl_xor_sync(0xFFFFFFFF, acc, 8);
    acc += __shfl_xor_sync(0xFFFFFFFF, acc, 4);
    acc += __shfl_xor_sync(0xFFFFFFFF, acc, 2);
    acc += __shfl_xor_sync(0xFFFFFFFF, acc, 1);
    if (lane == 0) red[wid] = acc;
    __syncthreads();
    if (tid == 0) {
        float s = 0.f;
        #pragma unroll
        for (int w = 0; w < 8; w++) s += red[w];
        atomicAdd(&g_loss, -(double)s);
    }
}

__global__ void final_kernel(float* out) { out[0] = (float)g_loss; }

extern "C" void kernel_launch(void* const* d_in, const int* in_sizes, int n_in,
                              void* d_out, int out_size) {
    const float* out1  = (const float*)d_in[0];
    const float* out2  = (const float*)d_in[1];
    const float* label = (const float*)d_in[2];

    cudaFuncSetAttribute(pass1_sums, cudaFuncAttributeMaxDynamicSharedMemorySize, SMEM_P1);
    cudaFuncSetAttribute(pass2_fused, cudaFuncAttributeMaxDynamicSharedMemorySize, SMEM_P2);

    prep_kernel<<<(Nn * Mm / 4 + 255) / 256, 256>>>(out1, out2);
    dim3 grid(Nn / 128, Nn / 128);
    pass1_sums<<<grid, 256, SMEM_P1>>>();
    recip_kernel<<<32, 256>>>();
    pass2_fused<<<grid, 256, SMEM_P2>>>(label);
    final_kernel<<<1, 1>>>((float*)d_out);
}

// round 11
// speedup vs baseline: 1.5528x; 1.1523x over previous
#include <cuda_runtime.h>
#include <cuda_fp16.h>
#include <cstdint>

#define Nn 8192
#define Mm 128
#define EPSf 1e-4f
#define LDA 136   // fp16 elems per smem tile row (128 + 8 pad)

// ---------------- device scratch (allocation-free) ----------------
static __device__ __half g_A16[(size_t)Nn * Mm];  // out2 fp16
static __device__ __half g_B16[(size_t)Nn * Mm];  // out1 fp16
static __device__ float  g_Z[Nn];
static __device__ float  g_W[Nn];
static __device__ float  g_rZ[Nn];
static __device__ float  g_rW[Nn];
static __device__ double g_loss;

__device__ __forceinline__ uint32_t smem_u32(const void* p) {
    uint32_t a;
    asm("{ .reg .u64 t; cvta.to.shared.u64 t, %1; cvt.u32.u64 %0, t; }" : "=r"(a) : "l"(p));
    return a;
}
__device__ __forceinline__ void ldmx4(uint32_t* r, uint32_t addr) {
    asm volatile("ldmatrix.sync.aligned.m8n8.x4.shared.b16 {%0,%1,%2,%3}, [%4];"
                 : "=r"(r[0]), "=r"(r[1]), "=r"(r[2]), "=r"(r[3]) : "r"(addr));
}
// fp16-accumulator MMA: D(half2 x2) = A*B + D
__device__ __forceinline__ void mma16816h(uint32_t& c0, uint32_t& c1,
                                          const uint32_t* a, uint32_t b0, uint32_t b1) {
    asm volatile(
        "mma.sync.aligned.m16n8k16.row.col.f16.f16.f16.f16 "
        "{%0,%1}, {%2,%3,%4,%5}, {%6,%7}, {%0,%1};"
        : "+r"(c0), "+r"(c1)
        : "r"(a[0]), "r"(a[1]), "r"(a[2]), "r"(a[3]), "r"(b0), "r"(b1));
}

__global__ void prep_kernel(const float* __restrict__ out1, const float* __restrict__ out2) {
    int t = blockIdx.x * blockDim.x + threadIdx.x;
    if (t < Nn * Mm / 4) {
        float4 a = *(const float4*)&out2[(size_t)t * 4];
        float4 b = *(const float4*)&out1[(size_t)t * 4];
        __half2 a0 = __float22half2_rn(make_float2(a.x, a.y));
        __half2 a1 = __float22half2_rn(make_float2(a.z, a.w));
        __half2 b0 = __float22half2_rn(make_float2(b.x, b.y));
        __half2 b1 = __float22half2_rn(make_float2(b.z, b.w));
        *(uint2*)&g_A16[(size_t)t * 4] = make_uint2(*(uint32_t*)&a0, *(uint32_t*)&a1);
        *(uint2*)&g_B16[(size_t)t * 4] = make_uint2(*(uint32_t*)&b0, *(uint32_t*)&b1);
    }
    if (t < Nn) { g_Z[t] = 0.0f; g_W[t] = 0.0f; }
    if (t == 0) g_loss = 0.0;
}

#define T_ELEMS (128 * LDA)
#define SMEM_BYTES (2 * T_ELEMS * 2)          // 69632 -> 3 CTAs/SM (smem-wise)

// tile loader: A,B 128 rows of fp16 -> padded smem
__device__ __forceinline__ void load_tiles(__half* At, __half* Bt, int i0, int j0, int tid) {
    #pragma unroll 8
    for (int t = tid; t < 2048; t += 256) {
        int row = t >> 4, q = (t & 15) * 8;
        *(uint4*)&At[row * LDA + q] = *(const uint4*)&g_A16[(size_t)(i0 + row) * Mm + q];
        *(uint4*)&Bt[row * LDA + q] = *(const uint4*)&g_B16[(size_t)(j0 + row) * Mm + q];
    }
}

// MMA body, warp tile 32(m) x 64(n), fp16 accum: ch[2][8][2] (half2 words)
__device__ __forceinline__ void mma_tile_h(uint32_t sA, uint32_t sB, int m0w, int n0w,
                                           int lane, uint32_t ch[2][8][2]) {
    const int aro = (lane & 7) + ((lane >> 3) & 1) * 8;
    const int ako = ((lane >> 4) & 1) * 8;
    const int bro = (lane & 7) + ((lane >> 4) & 1) * 8;
    const int bko = ((lane >> 3) & 1) * 8;
    const uint32_t aoff = (uint32_t)(((m0w + aro) * LDA + ako) * 2);
    uint32_t boff[4];
    #pragma unroll
    for (int p = 0; p < 4; p++)
        boff[p] = (uint32_t)(((n0w + p * 16 + bro) * LDA + bko) * 2);

    #pragma unroll
    for (int kk = 0; kk < 8; kk++) {
        const uint32_t kb = (uint32_t)(kk * 32);
        uint32_t av[2][4], bv[4][4];
        #pragma unroll
        for (int mt = 0; mt < 2; mt++)
            ldmx4(av[mt], sA + aoff + (uint32_t)(mt * 16 * LDA * 2) + kb);
        #pragma unroll
        for (int p = 0; p < 4; p++)
            ldmx4(bv[p], sB + boff[p] + kb);
        #pragma unroll
        for (int mt = 0; mt < 2; mt++)
            #pragma unroll
            for (int nt = 0; nt < 8; nt++) {
                const int p = nt >> 1, r = (nt & 1) * 2;
                mma16816h(ch[mt][nt][0], ch[mt][nt][1], av[mt], bv[p][r], bv[p][r + 1]);
            }
    }
}

// ---------------- Pass 1: GEMM -> exp -> row/col sums ----------------
__global__ __launch_bounds__(256, 3) void pass1_sums() {
    extern __shared__ char sm[];
    __half* At = (__half*)sm;
    __half* Bt = At + T_ELEMS;

    const int tid = threadIdx.x, wid = tid >> 5, lane = tid & 31;
    const int i0 = blockIdx.y * 128, j0 = blockIdx.x * 128;
    const int m0w = (wid & 3) * 32, n0w = (wid >> 2) * 64;

    load_tiles(At, Bt, i0, j0, tid);
    __syncthreads();

    uint32_t ch[2][8][2] = {};
    mma_tile_h(smem_u32(At), smem_u32(Bt), m0w, n0w, lane, ch);

    // per-nt consume: exp, row-sum accumulation, col-sum shuffles (nothing held live)
    float rs[2][2] = {{0.f, 0.f}, {0.f, 0.f}};
    #pragma unroll
    for (int nt = 0; nt < 8; nt++) {
        float2 e00 = __half22float2(*(__half2*)&ch[0][nt][0]);  // mt0, rows r
        float2 e01 = __half22float2(*(__half2*)&ch[0][nt][1]);  // mt0, rows r+8
        float2 e10 = __half22float2(*(__half2*)&ch[1][nt][0]);  // mt1
        float2 e11 = __half22float2(*(__half2*)&ch[1][nt][1]);
        e00.x = __expf(e00.x); e00.y = __expf(e00.y);
        e01.x = __expf(e01.x); e01.y = __expf(e01.y);
        e10.x = __expf(e10.x); e10.y = __expf(e10.y);
        e11.x = __expf(e11.x); e11.y = __expf(e11.y);

        rs[0][0] += e00.x + e00.y;  rs[0][1] += e01.x + e01.y;
        rs[1][0] += e10.x + e10.y;  rs[1][1] += e11.x + e11.y;

        float v0 = e00.x + e01.x + e10.x + e11.x;
        float v1 = e00.y + e01.y + e10.y + e11.y;
        v0 += __shfl_xor_sync(0xFFFFFFFF, v0, 4);
        v0 += __shfl_xor_sync(0xFFFFFFFF, v0, 8);
        v0 += __shfl_xor_sync(0xFFFFFFFF, v0, 16);
        v1 += __shfl_xor_sync(0xFFFFFFFF, v1, 4);
        v1 += __shfl_xor_sync(0xFFFFFFFF, v1, 8);
        v1 += __shfl_xor_sync(0xFFFFFFFF, v1, 16);
        if (lane < 4) {
            int col = j0 + n0w + nt * 8 + lane * 2;
            atomicAdd(&g_W[col], v0);
            atomicAdd(&g_W[col + 1], v1);
        }
    }
    #pragma unroll
    for (int mt = 0; mt < 2; mt++) {
        float r0 = rs[mt][0], r1 = rs[mt][1];
        r0 += __shfl_xor_sync(0xFFFFFFFF, r0, 1);
        r0 += __shfl_xor_sync(0xFFFFFFFF, r0, 2);
        r1 += __shfl_xor_sync(0xFFFFFFFF, r1, 1);
        r1 += __shfl_xor_sync(0xFFFFFFFF, r1, 2);
        if ((lane & 3) == 0) {
            atomicAdd(&g_Z[i0 + m0w + mt * 16 + (lane >> 2)], r0);
            atomicAdd(&g_Z[i0 + m0w + mt * 16 + 8 + (lane >> 2)], r1);
        }
    }
}

__global__ void recip_kernel() {
    int i = blockIdx.x * blockDim.x + threadIdx.x;
    if (i < Nn) { g_rZ[i] = 1.0f / g_Z[i]; g_rW[i] = 1.0f / g_W[i]; }
}

// ---------------- Pass 2: GEMM -> stage (overlay A tile) -> coalesced fused loss ----------
__global__ __launch_bounds__(256, 3) void pass2_fused(const float* __restrict__ label) {
    extern __shared__ char sm[];
    __half* At = (__half*)sm;
    __half* Bt = At + T_ELEMS;
    uint32_t* stage = (uint32_t*)sm;   // overlays A tile (exactly 34816 B = 128 x 68 words)

    const int tid = threadIdx.x, wid = tid >> 5, lane = tid & 31;
    const int i0 = blockIdx.y * 128, j0 = blockIdx.x * 128;
    const int m0w = (wid & 3) * 32, n0w = (wid >> 2) * 64;

    load_tiles(At, Bt, i0, j0, tid);
    __syncthreads();

    uint32_t ch[2][8][2] = {};
    mma_tile_h(smem_u32(At), smem_u32(Bt), m0w, n0w, lane, ch);

    __syncthreads();   // all ldmatrix done; A-tile region reusable

    // stage fp16 fragments directly (no conversion needed)
    #pragma unroll
    for (int mt = 0; mt < 2; mt++)
        #pragma unroll
        for (int nt = 0; nt < 8; nt++) {
            int row = m0w + mt * 16 + (lane >> 2);
            int cw  = (n0w + nt * 8 + (lane & 3) * 2) >> 1;
            stage[(size_t)row * 68 + cw]       = ch[mt][nt][0];
            stage[(size_t)(row + 8) * 68 + cw] = ch[mt][nt][1];
        }
    __syncthreads();

    // coalesced epilogue: half-warp per row; lane16 covers 8 cols
    const int hw  = lane >> 4;
    const int l16 = lane & 15;
    const int colb = l16 * 8;
    float acc = 0.f;

    #pragma unroll
    for (int s8 = 0; s8 < 8; s8++) {
        const int r  = wid * 16 + s8 * 2 + hw;
        const float rZ = g_rZ[i0 + r];
        uint4 sv = *(const uint4*)&stage[(size_t)r * 68 + l16 * 4];
        const float* lp = &label[(size_t)(i0 + r) * Nn + j0 + colb];
        float4 la0 = *(const float4*)lp;
        float4 la1 = *(const float4*)(lp + 4);
        float4 w0  = *(const float4*)&g_rW[j0 + colb];
        float4 w1  = *(const float4*)&g_rW[j0 + colb + 4];

        float2 s0 = __half22float2(*(__half2*)&sv.x);
        float2 s1 = __half22float2(*(__half2*)&sv.y);
        float2 s2 = __half22float2(*(__half2*)&sv.z);
        float2 s3 = __half22float2(*(__half2*)&sv.w);

        float e0 = __expf(s0.x), e1 = __expf(s0.y), e2 = __expf(s1.x), e3 = __expf(s1.y);
        float e4 = __expf(s2.x), e5 = __expf(s2.y), e6 = __expf(s3.x), e7 = __expf(s3.y);

        acc += la0.x * __logf(fmaf(e0, rZ, EPSf) * fmaf(e0, w0.x, EPSf));
        acc += la0.y * __logf(fmaf(e1, rZ, EPSf) * fmaf(e1, w0.y, EPSf));
        acc += la0.z * __logf(fmaf(e2, rZ, EPSf) * fmaf(e2, w0.z, EPSf));
        acc += la0.w * __logf(fmaf(e3, rZ, EPSf) * fmaf(e3, w0.w, EPSf));
        acc += la1.x * __logf(fmaf(e4, rZ, EPSf) * fmaf(e4, w1.x, EPSf));
        acc += la1.y * __logf(fmaf(e5, rZ, EPSf) * fmaf(e5, w1.y, EPSf));
        acc += la1.z * __logf(fmaf(e6, rZ, EPSf) * fmaf(e6, w1.z, EPSf));
        acc += la1.w * __logf(fmaf(e7, rZ, EPSf) * fmaf(e7, w1.w, EPSf));
    }

    __syncthreads();
    float* red = (float*)sm;
    acc += __shfl_xor_sync(0xFFFFFFFF, acc, 16);
    acc += __shfl_xor_sync(0xFFFFFFFF, acc, 8);
    acc += __shfl_xor_sync(0xFFFFFFFF, acc, 4);
    acc += __shfl_xor_sync(0xFFFFFFFF, acc, 2);
    acc += __shfl_xor_sync(0xFFFFFFFF, acc, 1);
    if (lane == 0) red[wid] = acc;
    __syncthreads();
    if (tid == 0) {
        float s = 0.f;
        #pragma unroll
        for (int w = 0; w < 8; w++) s += red[w];
        atomicAdd(&g_loss, -(double)s);
    }
}

__global__ void final_kernel(float* out) { out[0] = (float)g_loss; }

extern "C" void kernel_launch(void* const* d_in, const int* in_sizes, int n_in,
                              void* d_out, int out_size) {
    const float* out1  = (const float*)d_in[0];
    const float* out2  = (const float*)d_in[1];
    const float* label = (const float*)d_in[2];

    cudaFuncSetAttribute(pass1_sums, cudaFuncAttributeMaxDynamicSharedMemorySize, SMEM_BYTES);
    cudaFuncSetAttribute(pass2_fused, cudaFuncAttributeMaxDynamicSharedMemorySize, SMEM_BYTES);

    prep_kernel<<<(Nn * Mm / 4 + 255) / 256, 256>>>(out1, out2);
    dim3 grid(Nn / 128, Nn / 128);
    pass1_sums<<<grid, 256, SMEM_BYTES>>>();
    recip_kernel<<<32, 256>>>();
    pass2_fused<<<grid, 256, SMEM_BYTES>>>(label);
    final_kernel<<<1, 1>>>((float*)d_out);
}